// round 4
// baseline (speedup 1.0000x reference)
#include <cuda_runtime.h>
#include <math.h>

#define Bb 32
#define Qq 900
#define Tt 300
#define Cc 256

#define NTH 64
#define NWARP (NTH/32)
#define COLS_PER 15   // 64*15 = 960 >= 900

// ---- scratch (static device globals; no allocation) ----
__device__ float g_cmatT[(size_t)Bb * Tt * Qq];   // [b][t][q]
__device__ float g_rowmax[Bb * Qq];
__device__ float g_rowsum[Bb * Qq];

// monotone u64 encoding of fp64 (integer order == fp64 order)
__device__ __forceinline__ unsigned long long enc_f64(double d) {
    long long b = __double_as_longlong(d);
    if (b == (long long)0x8000000000000000LL) b = 0;   // -0 -> +0
    unsigned long long u = (unsigned long long)b;
    return (b < 0) ? ~u : (u | 0x8000000000000000ULL);
}
__device__ __forceinline__ double dec_f64(unsigned long long k) {
    unsigned long long u = (k & 0x8000000000000000ULL)
                         ? (k ^ 0x8000000000000000ULL) : ~k;
    return __longlong_as_double((long long)u);
}

// ============================================================
// Kernel 1: per-(b,q) softmax stats
// ============================================================
__global__ void row_stats_kernel(const float* __restrict__ logits) {
    int warp_in_blk = threadIdx.x >> 5;
    int lane = threadIdx.x & 31;
    int row = blockIdx.x * (blockDim.x >> 5) + warp_in_blk;
    if (row >= Bb * Qq) return;
    const float* lp = logits + (size_t)row * Cc;

    float m = -INFINITY;
    #pragma unroll
    for (int c = lane; c < Cc; c += 32) m = fmaxf(m, lp[c]);
    #pragma unroll
    for (int o = 16; o; o >>= 1) m = fmaxf(m, __shfl_xor_sync(0xFFFFFFFFu, m, o));

    float s = 0.f;
    #pragma unroll
    for (int c = lane; c < Cc; c += 32) s += expf(lp[c] - m);
    #pragma unroll
    for (int o = 16; o; o >>= 1) s += __shfl_xor_sync(0xFFFFFFFFu, s, o);

    if (lane == 0) { g_rowmax[row] = m; g_rowsum[row] = s; }
}

// ============================================================
// Kernel 2: cost matrix, one block per (b,q), thread t = target
// ============================================================
__global__ void cost_kernel(const float* __restrict__ logits,
                            const float* __restrict__ pboxes,
                            const float* __restrict__ pcut,
                            const int*   __restrict__ tlabels,
                            const float* __restrict__ tboxes,
                            const float* __restrict__ tcut,
                            float* __restrict__ out) {
    int bq = blockIdx.x;
    int b = bq / Qq;
    int t = threadIdx.x;
    if (t >= Tt) return;

    float px0 = pboxes[bq * 4 + 0];
    float py0 = pboxes[bq * 4 + 1];
    float px1 = pboxes[bq * 4 + 2];
    float py1 = pboxes[bq * 4 + 3];
    float pc  = pcut[bq];
    float rm  = g_rowmax[bq];
    float rs  = g_rowsum[bq];
    float area_p = (px1 - px0) * (py1 - py0);

    int bt = b * Tt + t;
    int lbl = tlabels[bt];
    float logit = logits[(size_t)bq * Cc + lbl];
    float cost_class = -(expf(logit - rm) / rs);

    float tx0 = tboxes[bt * 4 + 0];
    float ty0 = tboxes[bt * 4 + 1];
    float tx1 = tboxes[bt * 4 + 2];
    float ty1 = tboxes[bt * 4 + 3];

    float cost_bbox = fabsf(px0 - tx0) + fabsf(py0 - ty0)
                    + fabsf(px1 - tx1) + fabsf(py1 - ty1);

    float area_t = (tx1 - tx0) * (ty1 - ty0);
    float iw = fmaxf(fminf(px1, tx1) - fmaxf(px0, tx0), 0.f);
    float ih = fmaxf(fminf(py1, ty1) - fmaxf(py0, ty0), 0.f);
    float inter = iw * ih;
    float uni = area_p + area_t - inter;
    float iou = inter / uni;
    float ew = fmaxf(fmaxf(px1, tx1) - fminf(px0, tx0), 0.f);
    float eh = fmaxf(fmaxf(py1, ty1) - fminf(py0, ty0), 0.f);
    float enc = ew * eh;
    float giou = iou - (enc - uni) / enc;

    float cost_cutin = fabsf(pc - tcut[bt]);

    out[(size_t)bq * Tt + t] =
        5.0f * cost_bbox + 1.0f * cost_class - 2.0f * giou + 2.0f * cost_cutin;
}

// ============================================================
// Kernel 3: transpose Cmat[b][q][t] -> g_cmatT[b][t][q]
// ============================================================
__global__ void transpose_kernel(const float* __restrict__ cm) {
    __shared__ float tile[32][33];
    int b  = blockIdx.z;
    int t0 = blockIdx.x * 32;
    int q0 = blockIdx.y * 32;

    for (int r = threadIdx.y; r < 32; r += blockDim.y) {
        int q = q0 + r, t = t0 + threadIdx.x;
        if (q < Qq && t < Tt)
            tile[r][threadIdx.x] = cm[((size_t)b * Qq + q) * Tt + t];
    }
    __syncthreads();
    for (int r = threadIdx.y; r < 32; r += blockDim.y) {
        int t = t0 + r, q = q0 + threadIdx.x;
        if (q < Qq && t < Tt)
            g_cmatT[((size_t)b * Tt + t) * Qq + q] = tile[threadIdx.x][r];
    }
}

// ============================================================
// Kernel 4: Jonker-Volgenant, 64 threads/block (2 warps), 15 cols
// per thread. fp64 arithmetic identical to numpy; fp64 slot compares
// (ILP across slots); depth-4 lane tournament (keep-left on ties =
// min-j, since slot j increases with s); warp reduce via 3x REDUX on
// the monotone-u64 key; single __syncthreads per step.
// ============================================================
__global__ void __launch_bounds__(NTH)
solver_kernel(float* __restrict__ out_qidx, float* __restrict__ out_tidx) {
    int b = blockIdx.x;
    const float* costT = g_cmatT + (size_t)b * Tt * Qq;

    __shared__ double u[Tt + 1];
    __shared__ int    p[Qq + 1];
    __shared__ int    way[Qq + 1];
    __shared__ unsigned long long red_k[2][NWARP];
    __shared__ int                red_j[2][NWARP];

    const int tid  = threadIdx.x;
    const int lane = tid & 31;
    const int wrp  = tid >> 5;

    for (int k = tid; k <= Qq; k += NTH) p[k] = 0;
    for (int k = tid; k <= Tt; k += NTH) u[k] = 0.0;

    double v[COLS_PER];
    #pragma unroll
    for (int s = 0; s < COLS_PER; s++) v[s] = 0.0;
    __syncthreads();

    const double DINF = (double)INFINITY;

    for (int i = 1; i <= Tt; i++) {
        if (tid == 0) p[0] = i;
        unsigned usedmask = 0;
        double minv[COLS_PER];
        int    rows[COLS_PER];          // matched row of owned used col
        #pragma unroll
        for (int s = 0; s < COLS_PER; s++) minv[s] = DINF;

        // prefetch cost row (i-1)
        float cpre[COLS_PER];
        #pragma unroll
        for (int s = 0; s < COLS_PER; s++) {
            int j = tid + s * NTH + 1;
            if (j <= Qq) cpre[s] = __ldg(&costT[(size_t)(i - 1) * Qq + (j - 1)]);
        }

        int j0 = 0, i0 = i, parity = 0, j1 = 0;
        double ui0 = u[i];

        while (true) {
            // mark j0 used; cache its matched row (i0 == p[j0] right now)
            if (j0 > 0) {
                int rel = j0 - 1;
                if ((rel & (NTH - 1)) == tid) {
                    int s0 = rel / NTH;
                    usedmask |= 1u << s0;
                    rows[s0] = i0;
                }
            }

            // --- scan owned free columns (fp64, independent per slot) ---
            double tval[COLS_PER + 1];
            #pragma unroll
            for (int s = 0; s < COLS_PER; s++) {
                int j = tid + s * NTH + 1;
                bool free_ok = (j <= Qq) && !((usedmask >> s) & 1u);
                if (free_ok) {
                    double cur = (double)cpre[s] - ui0 - v[s];
                    if (cur < minv[s]) { minv[s] = cur; way[j] = j0; }
                    tval[s] = minv[s];
                } else {
                    tval[s] = DINF;
                }
            }
            tval[COLS_PER] = DINF;   // pad to 16

            // --- lane-local tournament, depth 4; keep-left on tie = min j ---
            double t8[8]; int i8[8];
            #pragma unroll
            for (int k = 0; k < 8; k++) {
                double a = tval[2 * k], c = tval[2 * k + 1];
                if (c < a) { t8[k] = c; i8[k] = 2 * k + 1; }
                else       { t8[k] = a; i8[k] = 2 * k; }
            }
            double t4[4]; int i4[4];
            #pragma unroll
            for (int k = 0; k < 4; k++) {
                if (t8[2 * k + 1] < t8[2 * k]) { t4[k] = t8[2 * k + 1]; i4[k] = i8[2 * k + 1]; }
                else                           { t4[k] = t8[2 * k];     i4[k] = i8[2 * k]; }
            }
            double t2[2]; int i2[2];
            #pragma unroll
            for (int k = 0; k < 2; k++) {
                if (t4[2 * k + 1] < t4[2 * k]) { t2[k] = t4[2 * k + 1]; i2[k] = i4[2 * k + 1]; }
                else                           { t2[k] = t4[2 * k];     i2[k] = i4[2 * k]; }
            }
            double lval; int lslot;
            if (t2[1] < t2[0]) { lval = t2[1]; lslot = i2[1]; }
            else               { lval = t2[0]; lslot = i2[0]; }
            int lj = tid + lslot * NTH + 1;              // owned j of lane winner

            // --- warp reduce via 3x REDUX on split monotone key ---
            unsigned long long lkey = enc_f64(lval);
            unsigned hi = (unsigned)(lkey >> 32);
            unsigned lo = (unsigned)lkey;
            unsigned mhi = __reduce_min_sync(0xFFFFFFFFu, hi);
            unsigned mlo = __reduce_min_sync(0xFFFFFFFFu,
                              (hi == mhi) ? lo : 0xFFFFFFFFu);
            int wj = (int)__reduce_min_sync(0xFFFFFFFFu,
                              (hi == mhi && lo == mlo) ? (unsigned)lj : 0x7FFFFFFFu);
            unsigned long long wk = ((unsigned long long)mhi << 32) | mlo;

            if (lane == 0) { red_k[parity][wrp] = wk; red_j[parity][wrp] = wj; }
            __syncthreads();   // the ONLY barrier in the step

            // --- cross-warp combine (2 entries), all threads ---
            unsigned long long k0 = red_k[parity][0], k1 = red_k[parity][1];
            int e0 = red_j[parity][0], e1 = red_j[parity][1];
            unsigned long long kw;
            if (k1 < k0 || (k1 == k0 && e1 < e0)) { kw = k1; j1 = e1; }
            else                                  { kw = k0; j1 = e0; }
            double delta = dec_f64(kw);

            // next row: read early (not touched by this step's update)
            i0 = p[j1];
            if (i0 > 0) {
                ui0 = u[i0];
                #pragma unroll
                for (int s = 0; s < COLS_PER; s++) {
                    int j = tid + s * NTH + 1;
                    if (j <= Qq) cpre[s] = __ldg(&costT[(size_t)(i0 - 1) * Qq + (j - 1)]);
                }
            }

            // --- potential updates (before break check, like the reference) ---
            if (tid == 0) u[i] += delta;
            #pragma unroll
            for (int s = 0; s < COLS_PER; s++) {
                int j = tid + s * NTH + 1;
                if (j <= Qq) {
                    if ((usedmask >> s) & 1u) { u[rows[s]] += delta; v[s] -= delta; }
                    else                      { minv[s] -= delta; }
                }
            }

            if (i0 == 0) break;
            j0 = j1;
            parity ^= 1;
        }

        // augment along way[] chain
        if (tid == 0) {
            int jj = j1;
            while (jj) { int jn = way[jj]; p[jj] = p[jn]; jj = jn; }
        }
        __syncthreads();
    }

    for (int j = tid + 1; j <= Qq; j += NTH)
        if (p[j] > 0) out_qidx[b * Tt + (p[j] - 1)] = (float)(j - 1);
    for (int t = tid; t < Tt; t += NTH)
        out_tidx[b * Tt + t] = (float)t;
}

// ============================================================
extern "C" void kernel_launch(void* const* d_in, const int* in_sizes, int n_in,
                              void* d_out, int out_size) {
    const float* pred_logits = (const float*)d_in[0];
    const float* pred_boxes  = (const float*)d_in[1];
    const float* pred_cutin  = (const float*)d_in[2];
    const int*   tgt_labels  = (const int*)  d_in[3];
    const float* tgt_boxes   = (const float*)d_in[4];
    const float* tgt_cutin   = (const float*)d_in[5];

    float* out = (float*)d_out;
    float* out_cmat = out;                                  // B*Q*T
    float* out_qidx = out + (size_t)Bb * Qq * Tt;           // B*T
    float* out_tidx = out_qidx + (size_t)Bb * Tt;           // B*T

    {
        int rows = Bb * Qq;
        int warps_per_blk = 8;
        int blks = (rows + warps_per_blk - 1) / warps_per_blk;
        row_stats_kernel<<<blks, warps_per_blk * 32>>>(pred_logits);
    }
    cost_kernel<<<Bb * Qq, 320>>>(pred_logits, pred_boxes, pred_cutin,
                                  tgt_labels, tgt_boxes, tgt_cutin, out_cmat);
    {
        dim3 grid((Tt + 31) / 32, (Qq + 31) / 32, Bb);
        dim3 blk(32, 8);
        transpose_kernel<<<grid, blk>>>(out_cmat);
    }
    solver_kernel<<<Bb, NTH>>>(out_qidx, out_tidx);
}

// round 5
// speedup vs baseline: 1.2542x; 1.2542x over previous
#include <cuda_runtime.h>
#include <math.h>

#define Bb 32
#define Qq 900
#define Tt 300
#define Cc 256

#define NTH 128
#define NWARP (NTH/32)
#define COLS_PER 8   // ceil(900/128)

// ---- scratch (static device globals; no allocation) ----
__device__ float g_cmatT[(size_t)Bb * Tt * Qq];   // [b][t][q]
__device__ float g_rowmax[Bb * Qq];
__device__ float g_rowsum[Bb * Qq];

// monotone u64 encoding of fp64 (integer order == fp64 order; -0 -> +0)
__device__ __forceinline__ unsigned long long enc_f64(double d) {
    long long b = __double_as_longlong(d);
    if (b == (long long)0x8000000000000000LL) b = 0;   // -0 -> +0
    unsigned long long u = (unsigned long long)b;
    return (b < 0) ? ~u : (u | 0x8000000000000000ULL);
}
__device__ __forceinline__ double dec_f64(unsigned long long k) {
    unsigned long long u = (k & 0x8000000000000000ULL)
                         ? (k ^ 0x8000000000000000ULL) : ~k;
    return __longlong_as_double((long long)u);
}
#define KEY_INF 0xFFF0000000000000ULL   // enc_f64(+inf)

// ============================================================
// Kernel 1: per-(b,q) softmax stats
// ============================================================
__global__ void row_stats_kernel(const float* __restrict__ logits) {
    int warp_in_blk = threadIdx.x >> 5;
    int lane = threadIdx.x & 31;
    int row = blockIdx.x * (blockDim.x >> 5) + warp_in_blk;
    if (row >= Bb * Qq) return;
    const float* lp = logits + (size_t)row * Cc;

    float m = -INFINITY;
    #pragma unroll
    for (int c = lane; c < Cc; c += 32) m = fmaxf(m, lp[c]);
    #pragma unroll
    for (int o = 16; o; o >>= 1) m = fmaxf(m, __shfl_xor_sync(0xFFFFFFFFu, m, o));

    float s = 0.f;
    #pragma unroll
    for (int c = lane; c < Cc; c += 32) s += expf(lp[c] - m);
    #pragma unroll
    for (int o = 16; o; o >>= 1) s += __shfl_xor_sync(0xFFFFFFFFu, s, o);

    if (lane == 0) { g_rowmax[row] = m; g_rowsum[row] = s; }
}

// ============================================================
// Kernel 2: cost matrix, one block per (b,q), thread t = target
// ============================================================
__global__ void cost_kernel(const float* __restrict__ logits,
                            const float* __restrict__ pboxes,
                            const float* __restrict__ pcut,
                            const int*   __restrict__ tlabels,
                            const float* __restrict__ tboxes,
                            const float* __restrict__ tcut,
                            float* __restrict__ out) {
    int bq = blockIdx.x;
    int b = bq / Qq;
    int t = threadIdx.x;
    if (t >= Tt) return;

    float px0 = pboxes[bq * 4 + 0];
    float py0 = pboxes[bq * 4 + 1];
    float px1 = pboxes[bq * 4 + 2];
    float py1 = pboxes[bq * 4 + 3];
    float pc  = pcut[bq];
    float rm  = g_rowmax[bq];
    float rs  = g_rowsum[bq];
    float area_p = (px1 - px0) * (py1 - py0);

    int bt = b * Tt + t;
    int lbl = tlabels[bt];
    float logit = logits[(size_t)bq * Cc + lbl];
    float cost_class = -(expf(logit - rm) / rs);

    float tx0 = tboxes[bt * 4 + 0];
    float ty0 = tboxes[bt * 4 + 1];
    float tx1 = tboxes[bt * 4 + 2];
    float ty1 = tboxes[bt * 4 + 3];

    float cost_bbox = fabsf(px0 - tx0) + fabsf(py0 - ty0)
                    + fabsf(px1 - tx1) + fabsf(py1 - ty1);

    float area_t = (tx1 - tx0) * (ty1 - ty0);
    float iw = fmaxf(fminf(px1, tx1) - fmaxf(px0, tx0), 0.f);
    float ih = fmaxf(fminf(py1, ty1) - fmaxf(py0, ty0), 0.f);
    float inter = iw * ih;
    float uni = area_p + area_t - inter;
    float iou = inter / uni;
    float ew = fmaxf(fmaxf(px1, tx1) - fminf(px0, tx0), 0.f);
    float eh = fmaxf(fmaxf(py1, ty1) - fminf(py0, ty0), 0.f);
    float enc = ew * eh;
    float giou = iou - (enc - uni) / enc;

    float cost_cutin = fabsf(pc - tcut[bt]);

    out[(size_t)bq * Tt + t] =
        5.0f * cost_bbox + 1.0f * cost_class - 2.0f * giou + 2.0f * cost_cutin;
}

// ============================================================
// Kernel 3: transpose Cmat[b][q][t] -> g_cmatT[b][t][q]
// ============================================================
__global__ void transpose_kernel(const float* __restrict__ cm) {
    __shared__ float tile[32][33];
    int b  = blockIdx.z;
    int t0 = blockIdx.x * 32;
    int q0 = blockIdx.y * 32;

    for (int r = threadIdx.y; r < 32; r += blockDim.y) {
        int q = q0 + r, t = t0 + threadIdx.x;
        if (q < Qq && t < Tt)
            tile[r][threadIdx.x] = cm[((size_t)b * Qq + q) * Tt + t];
    }
    __syncthreads();
    for (int r = threadIdx.y; r < 32; r += blockDim.y) {
        int t = t0 + r, q = q0 + threadIdx.x;
        if (q < Qq && t < Tt)
            g_cmatT[((size_t)b * Tt + t) * Qq + q] = tile[threadIdx.x][r];
    }
}

// ============================================================
// Kernel 4: Jonker-Volgenant. R2 structure (128 thr, 8 slots,
// fp64 scan + update, single barrier, row prefetch hidden under
// the update phase) with the reduction switched to integer keys:
// encode-at-tournament (8 ILP encodes), depth-3 int tournament,
// 3x REDUX warp reduce, int lexicographic cross-warp combine.
// ============================================================
__global__ void __launch_bounds__(NTH)
solver_kernel(float* __restrict__ out_qidx, float* __restrict__ out_tidx) {
    int b = blockIdx.x;
    const float* costT = g_cmatT + (size_t)b * Tt * Qq;

    __shared__ double u[Tt + 1];
    __shared__ int    p[Qq + 1];
    __shared__ int    way[Qq + 1];
    __shared__ unsigned long long red_k[2][NWARP];
    __shared__ int                red_j[2][NWARP];

    const int tid  = threadIdx.x;
    const int lane = tid & 31;
    const int wrp  = tid >> 5;

    for (int k = tid; k <= Qq; k += NTH) p[k] = 0;
    for (int k = tid; k <= Tt; k += NTH) u[k] = 0.0;

    double v[COLS_PER];
    #pragma unroll
    for (int s = 0; s < COLS_PER; s++) v[s] = 0.0;
    __syncthreads();

    const double DINF = (double)INFINITY;

    for (int i = 1; i <= Tt; i++) {
        if (tid == 0) p[0] = i;
        unsigned usedmask = 0;
        double minv[COLS_PER];
        int    rows[COLS_PER];          // matched row of owned used col
        #pragma unroll
        for (int s = 0; s < COLS_PER; s++) minv[s] = DINF;

        // prefetch cost row (i-1)
        float cpre[COLS_PER];
        #pragma unroll
        for (int s = 0; s < COLS_PER; s++) {
            int j = tid + s * NTH + 1;
            if (j <= Qq) cpre[s] = __ldg(&costT[(size_t)(i - 1) * Qq + (j - 1)]);
        }

        int j0 = 0, i0 = i, parity = 0, j1 = 0;
        double ui0 = u[i];

        while (true) {
            // mark j0 used; cache its matched row (i0 == p[j0] right now)
            if (j0 > 0) {
                int rel = j0 - 1;
                if ((rel & (NTH - 1)) == tid) {
                    int s0 = rel >> 7;
                    usedmask |= 1u << s0;
                    rows[s0] = i0;
                }
            }

            // --- scan owned free columns: pure fp64, independent slots ---
            unsigned long long key[COLS_PER];
            #pragma unroll
            for (int s = 0; s < COLS_PER; s++) {
                int j = tid + s * NTH + 1;
                if (j <= Qq && !((usedmask >> s) & 1u)) {
                    double cur = (double)cpre[s] - ui0 - v[s];
                    if (cur < minv[s]) { minv[s] = cur; way[j] = j0; }
                    key[s] = enc_f64(minv[s]);   // int encode, ILP across slots
                } else {
                    key[s] = KEY_INF;
                }
            }

            // --- integer tournament depth 3; keep-left on tie = min j ---
            unsigned long long k4[4]; int s4[4];
            #pragma unroll
            for (int k = 0; k < 4; k++) {
                if (key[2 * k + 1] < key[2 * k]) { k4[k] = key[2 * k + 1]; s4[k] = 2 * k + 1; }
                else                             { k4[k] = key[2 * k];     s4[k] = 2 * k; }
            }
            unsigned long long k2[2]; int s2[2];
            #pragma unroll
            for (int k = 0; k < 2; k++) {
                if (k4[2 * k + 1] < k4[2 * k]) { k2[k] = k4[2 * k + 1]; s2[k] = s4[2 * k + 1]; }
                else                           { k2[k] = k4[2 * k];     s2[k] = s4[2 * k]; }
            }
            unsigned long long lkey; int lslot;
            if (k2[1] < k2[0]) { lkey = k2[1]; lslot = s2[1]; }
            else               { lkey = k2[0]; lslot = s2[0]; }
            int lj = tid + lslot * NTH + 1;

            // --- warp reduce via 3x REDUX on split monotone key ---
            unsigned hi = (unsigned)(lkey >> 32);
            unsigned lo = (unsigned)lkey;
            unsigned mhi = __reduce_min_sync(0xFFFFFFFFu, hi);
            unsigned mlo = __reduce_min_sync(0xFFFFFFFFu,
                              (hi == mhi) ? lo : 0xFFFFFFFFu);
            int wj = (int)__reduce_min_sync(0xFFFFFFFFu,
                              (hi == mhi && lo == mlo) ? (unsigned)lj : 0x7FFFFFFFu);
            unsigned long long wk = ((unsigned long long)mhi << 32) | mlo;

            if (lane == 0) { red_k[parity][wrp] = wk; red_j[parity][wrp] = wj; }
            __syncthreads();   // the ONLY barrier in the step

            // --- integer lexicographic combine over 4 warp results ---
            unsigned long long c0 = red_k[parity][0], c1 = red_k[parity][1];
            unsigned long long c2 = red_k[parity][2], c3 = red_k[parity][3];
            int e0 = red_j[parity][0], e1 = red_j[parity][1];
            int e2 = red_j[parity][2], e3 = red_j[parity][3];
            unsigned long long ka; int ea;
            if (c1 < c0 || (c1 == c0 && e1 < e0)) { ka = c1; ea = e1; } else { ka = c0; ea = e0; }
            unsigned long long kb; int eb;
            if (c3 < c2 || (c3 == c2 && e3 < e2)) { kb = c3; eb = e3; } else { kb = c2; eb = e2; }
            unsigned long long kw;
            if (kb < ka || (kb == ka && eb < ea)) { kw = kb; j1 = eb; } else { kw = ka; j1 = ea; }
            double delta = dec_f64(kw);

            // next row: read early (not written by this step's update),
            // prefetch its cost values + u value (hidden under update)
            i0 = p[j1];
            if (i0 > 0) {
                ui0 = u[i0];
                #pragma unroll
                for (int s = 0; s < COLS_PER; s++) {
                    int j = tid + s * NTH + 1;
                    if (j <= Qq) cpre[s] = __ldg(&costT[(size_t)(i0 - 1) * Qq + (j - 1)]);
                }
            }

            // --- fp64 potential updates (ILP; also hides the prefetch) ---
            if (tid == 0) u[i] += delta;
            #pragma unroll
            for (int s = 0; s < COLS_PER; s++) {
                int j = tid + s * NTH + 1;
                if (j <= Qq) {
                    if ((usedmask >> s) & 1u) { u[rows[s]] += delta; v[s] -= delta; }
                    else                      { minv[s] -= delta; }
                }
            }

            if (i0 == 0) break;
            j0 = j1;
            parity ^= 1;
        }

        // augment along way[] chain
        if (tid == 0) {
            int jj = j1;
            while (jj) { int jn = way[jj]; p[jj] = p[jn]; jj = jn; }
        }
        __syncthreads();
    }

    for (int j = tid + 1; j <= Qq; j += NTH)
        if (p[j] > 0) out_qidx[b * Tt + (p[j] - 1)] = (float)(j - 1);
    for (int t = tid; t < Tt; t += NTH)
        out_tidx[b * Tt + t] = (float)t;
}

// ============================================================
extern "C" void kernel_launch(void* const* d_in, const int* in_sizes, int n_in,
                              void* d_out, int out_size) {
    const float* pred_logits = (const float*)d_in[0];
    const float* pred_boxes  = (const float*)d_in[1];
    const float* pred_cutin  = (const float*)d_in[2];
    const int*   tgt_labels  = (const int*)  d_in[3];
    const float* tgt_boxes   = (const float*)d_in[4];
    const float* tgt_cutin   = (const float*)d_in[5];

    float* out = (float*)d_out;
    float* out_cmat = out;                                  // B*Q*T
    float* out_qidx = out + (size_t)Bb * Qq * Tt;           // B*T
    float* out_tidx = out_qidx + (size_t)Bb * Tt;           // B*T

    {
        int rows = Bb * Qq;
        int warps_per_blk = 8;
        int blks = (rows + warps_per_blk - 1) / warps_per_blk;
        row_stats_kernel<<<blks, warps_per_blk * 32>>>(pred_logits);
    }
    cost_kernel<<<Bb * Qq, 320>>>(pred_logits, pred_boxes, pred_cutin,
                                  tgt_labels, tgt_boxes, tgt_cutin, out_cmat);
    {
        dim3 grid((Tt + 31) / 32, (Qq + 31) / 32, Bb);
        dim3 blk(32, 8);
        transpose_kernel<<<grid, blk>>>(out_cmat);
    }
    solver_kernel<<<Bb, NTH>>>(out_qidx, out_tidx);
}